// round 14
// baseline (speedup 1.0000x reference)
#include <cuda_runtime.h>
#include <cstdint>

typedef unsigned long long ull;
typedef unsigned int uint;

#define D_IN   4096
#define R_RANK 16
#define O_OUT  4096
#define M_TOT  8192
#define SCALE  2.0f          // alpha/rank = 32/16
#define KC     64            // K floats per pipeline chunk (p1)
#define NITER  (D_IN / KC)   // 64
#define MT     16            // tokens per CTA (p1)
#define NSTG   5             // pipeline depth (p1)

// ---- device scratch: h as plain float [m][16] ----
__device__ __align__(16) float g_h32[M_TOT * R_RANK];

// ---- async-copy helpers (sm_80 base ISA only) ----
__device__ __forceinline__ uint32_t smem_u32(const void* p) {
    uint32_t a;
    asm("{ .reg .u64 t; cvta.to.shared.u64 t, %1; cvt.u32.u64 %0, t; }"
        : "=r"(a) : "l"(p));
    return a;
}
__device__ __forceinline__ void cpa16(uint32_t dst, const void* src) {
    asm volatile("cp.async.cg.shared.global [%0], [%1], 16;"
                 :: "r"(dst), "l"(src) : "memory");
}
__device__ __forceinline__ void cpa_commit() {
    asm volatile("cp.async.commit_group;" ::: "memory");
}
__device__ __forceinline__ void cpa_wait3() {
    asm volatile("cp.async.wait_group 3;" ::: "memory");
}

// ---- tf32 mma helpers (base ISA, sm_80+) ----
__device__ __forceinline__ uint f2tf(float f) {   // round-to-nearest tf32
    uint r; asm("cvt.rna.tf32.f32 %0, %1;" : "=r"(r) : "f"(f)); return r;
}
__device__ __forceinline__ void mma8(float* d, uint a0, uint a1, uint a2, uint a3,
                                     uint b0, uint b1) {
    asm volatile(
        "mma.sync.aligned.m16n8k8.row.col.f32.tf32.tf32.f32 "
        "{%0,%1,%2,%3}, {%4,%5,%6,%7}, {%8,%9}, {%0,%1,%2,%3};"
        : "+f"(d[0]), "+f"(d[1]), "+f"(d[2]), "+f"(d[3])
        : "r"(a0), "r"(a1), "r"(a2), "r"(a3), "r"(b0), "r"(b1));
}

// ===================== kernel 1: h = SCALE * (x @ A^T), mma.sync tf32 =========
// 512 CTAs x 128 threads, MT=16 tokens/CTA, occ 5 (single wave, 740 slots).
// 4 warps = 1 m16-tile x 4 k-quarters. 5-stage single-sync cp.async pipeline,
// 4 chunks DRAM-in-flight (16 KB/CTA, ~3.5 CTA/SM -> ~56 KB/SM).
// Stage (floats): x[16][68] then raw A[16][68] -> 2176 floats = 8704 B.
#define XS_F     (MT * 68)               // 1088
#define STAGE_F  (XS_F + 16 * 68)        // 2176
#define SM1_F    (NSTG * STAGE_F)        // 10880 floats = 43520 B (static ok)

__device__ __forceinline__ void p1_stage(uint32_t sb, const float* x,
                                         const float* A, int m0, int c, int b,
                                         int tid) {
    const uint32_t base = sb + b * (STAGE_F * 4);
    #pragma unroll
    for (int t = 0; t < 2; ++t) {               // x: 16 rows x 16 16B-units
        int u = tid + t * 128;
        int row = u >> 4, q = u & 15;
        cpa16(base + (row * 68) * 4 + q * 16,
              x + (size_t)(m0 + row) * D_IN + c * KC + q * 4);
    }
    #pragma unroll
    for (int t = 0; t < 2; ++t) {               // raw A: 16 rows x 16 units
        int u = tid + t * 128;
        int row = u >> 4, q = u & 15;
        cpa16(base + (XS_F + row * 68) * 4 + q * 16,
              A + (size_t)row * D_IN + c * KC + q * 4);
    }
}

__global__ void __launch_bounds__(128, 4)
lora_mma1(const float* __restrict__ x, const float* __restrict__ A) {
    __shared__ __align__(16) float sm[SM1_F];
    const uint32_t sb = smem_u32(sm);

    const int tid  = threadIdx.x;
    const int lane = tid & 31;
    const int kh   = tid >> 5;       // k-quarter (0..3)
    const int m0   = blockIdx.x * MT;
    const int r0   = lane >> 2;
    const int c0   = lane & 3;

    float d[4][4];                   // [0:hi r0-7, 1:hi r8-15, 2:lo r0-7, 3:lo r8-15]
    #pragma unroll
    for (int nt = 0; nt < 4; ++nt)
        #pragma unroll
        for (int j = 0; j < 4; ++j) d[nt][j] = 0.0f;

    // prologue: stage chunks 0..3
    p1_stage(sb, x, A, m0, 0, 0, tid); cpa_commit();
    p1_stage(sb, x, A, m0, 1, 1, tid); cpa_commit();
    p1_stage(sb, x, A, m0, 2, 2, tid); cpa_commit();
    p1_stage(sb, x, A, m0, 3, 3, tid); cpa_commit();

    int b = 0;
    for (int i = 0; i < NITER; ++i) {
        cpa_wait3();          // chunk i landed (3 groups still pending)
        __syncthreads();      // visible to all; all warps past compute(i-1)

        // prefetch chunk i+4 into buffer (i+4)%5 == (i-1)%5 (freed by the sync)
        if (i + 4 < NITER) p1_stage(sb, x, A, m0, i + 4, (i + 4) % NSTG, tid);
        cpa_commit();

        const float* xw = sm + b * STAGE_F;
        const float* rw = sm + b * STAGE_F + XS_F;
        b = (b + 1 == NSTG) ? 0 : b + 1;

        #pragma unroll
        for (int ks = 0; ks < 2; ++ks) {
            const int k0 = kh * 16 + ks * 8 + c0;
            // A-operand fragment: x rows (tf32 rna, zero-mean)
            uint a0 = f2tf(xw[r0 * 68 + k0]);
            uint a1 = f2tf(xw[(r0 + 8) * 68 + k0]);
            uint a2 = f2tf(xw[r0 * 68 + k0 + 4]);
            uint a3 = f2tf(xw[(r0 + 8) * 68 + k0 + 4]);
            // B-operand: LoRA-A rows, hi/lo split (hi exact tf32)
            float v00 = rw[r0 * 68 + k0];
            float v01 = rw[r0 * 68 + k0 + 4];
            float v10 = rw[(r0 + 8) * 68 + k0];
            float v11 = rw[(r0 + 8) * 68 + k0 + 4];
            uint h00 = __float_as_uint(v00) & 0xFFFFE000u;
            uint h01 = __float_as_uint(v01) & 0xFFFFE000u;
            uint h10 = __float_as_uint(v10) & 0xFFFFE000u;
            uint h11 = __float_as_uint(v11) & 0xFFFFE000u;
            float l00 = v00 - __uint_as_float(h00);
            float l01 = v01 - __uint_as_float(h01);
            float l10 = v10 - __uint_as_float(h10);
            float l11 = v11 - __uint_as_float(h11);
            mma8(d[0], a0, a1, a2, a3, h00, h01);
            mma8(d[1], a0, a1, a2, a3, h10, h11);
            mma8(d[2], a0, a1, a2, a3, __float_as_uint(l00), __float_as_uint(l01));
            mma8(d[3], a0, a1, a2, a3, __float_as_uint(l10), __float_as_uint(l11));
        }
    }

    // k-quarter reduction via smem (buffers dead; region = first 1536 floats,
    // last-used for chunk 60 while final compute reads buf 3 -> no overlap).
    float* red = sm;
    if (kh != 0) {
        #pragma unroll
        for (int nt = 0; nt < 4; ++nt)
            #pragma unroll
            for (int j = 0; j < 4; ++j)
                red[(kh - 1) * 512 + nt * 128 + j * 32 + lane] = d[nt][j];
    }
    __syncthreads();
    if (kh == 0) {
        #pragma unroll
        for (int q = 0; q < 3; ++q)
            #pragma unroll
            for (int nt = 0; nt < 4; ++nt)
                #pragma unroll
                for (int j = 0; j < 4; ++j)
                    d[nt][j] += red[q * 512 + nt * 128 + j * 32 + lane];

        // fold hi+lo, scale, store plain-float h[m][16] (validated D mapping:
        // regs 0,1 -> row r0 cols 2c0,2c0+1; regs 2,3 -> row r0+8).
        float e0 = (d[0][0] + d[2][0]) * SCALE, e1 = (d[0][1] + d[2][1]) * SCALE;
        float e2 = (d[0][2] + d[2][2]) * SCALE, e3 = (d[0][3] + d[2][3]) * SCALE;
        float f0 = (d[1][0] + d[3][0]) * SCALE, f1 = (d[1][1] + d[3][1]) * SCALE;
        float f2 = (d[1][2] + d[3][2]) * SCALE, f3 = (d[1][3] + d[3][3]) * SCALE;
        *(float2*)(g_h32 + (size_t)(m0 + r0) * 16 + 2 * c0)          = make_float2(e0, e1);
        *(float2*)(g_h32 + (size_t)(m0 + r0) * 16 + 8 + 2 * c0)      = make_float2(f0, f1);
        *(float2*)(g_h32 + (size_t)(m0 + r0 + 8) * 16 + 2 * c0)      = make_float2(e2, e3);
        *(float2*)(g_h32 + (size_t)(m0 + r0 + 8) * 16 + 8 + 2 * c0)  = make_float2(f2, f3);
    }
}

// ===================== kernel 2: out = h @ B^T, mma.sync tf32 ================
// grid (M/64, O/256) = (128, 16) = 2048 CTAs x 128 threads (4 warps).
// Warp w: o-strip of 64 (8 n8-tiles), m covers 64 tokens (4 m16-tiles).
// B frags in regs (32/lane, loaded once, L2-hot); h staged in smem stride-20
// (conflict-free for the fragment LDS pattern). Raw tf32 both operands.
__global__ void __launch_bounds__(128, 4)
lora_mma2(const float* __restrict__ B, float* __restrict__ out) {
    __shared__ __align__(16) float sh[64 * 20];   // 5120 B

    const int tid  = threadIdx.x;
    const int lane = tid & 31;
    const int warp = tid >> 5;
    const int m0   = blockIdx.x * 64;
    const int o0   = blockIdx.y * 256 + warp * 64;
    const int r0   = lane >> 2;
    const int c0   = lane & 3;

    // B fragments: n-tile j, k-step ks -> B[o0 + j*8 + r0][ks*8 + c0 (+4)]
    uint bf[8][2][2];
    #pragma unroll
    for (int j = 0; j < 8; ++j) {
        const float* br = B + (size_t)(o0 + j * 8 + r0) * R_RANK;
        #pragma unroll
        for (int ks = 0; ks < 2; ++ks) {
            bf[j][ks][0] = f2tf(br[ks * 8 + c0]);
            bf[j][ks][1] = f2tf(br[ks * 8 + c0 + 4]);
        }
    }

    // Stage h tile [64][16] -> smem stride 20 (coalesced LDG.128, one-time STS)
    #pragma unroll
    for (int t = 0; t < 2; ++t) {
        int q = tid + t * 128;            // float4 index, 0..255
        int m = q >> 2, quad = q & 3;
        float4 v = ((const float4*)(g_h32 + (size_t)m0 * 16))[q];
        *(float4*)(sh + m * 20 + quad * 4) = v;
    }
    __syncthreads();

    #pragma unroll
    for (int mt = 0; mt < 4; ++mt) {
        const float* hw = sh + (mt * 16) * 20;
        // A-operand fragments for both k-steps (validated mapping)
        uint a[2][4];
        #pragma unroll
        for (int ks = 0; ks < 2; ++ks) {
            a[ks][0] = f2tf(hw[r0 * 20 + ks * 8 + c0]);
            a[ks][1] = f2tf(hw[(r0 + 8) * 20 + ks * 8 + c0]);
            a[ks][2] = f2tf(hw[r0 * 20 + ks * 8 + c0 + 4]);
            a[ks][3] = f2tf(hw[(r0 + 8) * 20 + ks * 8 + c0 + 4]);
        }

        float dd[8][4];
        #pragma unroll
        for (int j = 0; j < 8; ++j)
            #pragma unroll
            for (int k = 0; k < 4; ++k) dd[j][k] = 0.0f;

        #pragma unroll
        for (int j = 0; j < 8; ++j) {
            mma8(dd[j], a[0][0], a[0][1], a[0][2], a[0][3], bf[j][0][0], bf[j][0][1]);
            mma8(dd[j], a[1][0], a[1][1], a[1][2], a[1][3], bf[j][1][0], bf[j][1][1]);
        }

        // Store: D regs 0,1 -> row r0, cols 2c0,2c0+1 of n-tile j; regs 2,3 -> row r0+8.
        const int mrow = m0 + mt * 16 + r0;
        #pragma unroll
        for (int j = 0; j < 8; ++j) {
            int oc = o0 + j * 8 + 2 * c0;
            *(float2*)(out + (size_t)mrow * O_OUT + oc)       = make_float2(dd[j][0], dd[j][1]);
            *(float2*)(out + (size_t)(mrow + 8) * O_OUT + oc) = make_float2(dd[j][2], dd[j][3]);
        }
    }
}

extern "C" void kernel_launch(void* const* d_in, const int* in_sizes, int n_in,
                              void* d_out, int out_size) {
    const float* x = (const float*)d_in[0];
    const float* A = (const float*)d_in[1];   // [16, 4096]
    const float* B = (const float*)d_in[2];   // [4096, 16]
    float* out = (float*)d_out;

    lora_mma1<<<M_TOT / MT, 128>>>(x, A);     // 512 CTAs, single wave
    dim3 g2(M_TOT / 64, O_OUT / 256);         // (128, 16) = 2048 CTAs
    lora_mma2<<<g2, 128>>>(B, out);
}